// round 9
// baseline (speedup 1.0000x reference)
#include <cuda_runtime.h>
#include <cstdint>

// GRU: B=64, T=2048, I=256, H=256.  out = concat(out[B,T,H], hN[B,H]) fp32.
//
// 16 clusters x 8 CTAs (128 SMs). Cluster owns 4 batches; CTA rank owns
// j in [32r,32r+32) => fused rows {j,256+j,512+j}. Thread (r,kc) keeps
// 64 floats of W_hh row chunk + 64 floats of W_ih row chunk IN REGISTERS.
//
// Per step (critical path only carries the h-GEMM):
//   h-GEMM(t)  [K=256, all 12 warps]  -> accH
//   __syncthreads
//   elementwise GRU (128 thr) -> DSMEM h-broadcast to 8 CTAs
//   cluster.arrive                      (release)
//   x-GEMM(t+1) [K=256, all 12 warps] -> accX[pn]   } hides barrier
//   cp.async prefetch x(t+2)                        } latency + skew
//   cluster.wait                        (acquire)

static constexpr int B_  = 64;
static constexpr int T_  = 2048;
static constexpr int I_  = 256;
static constexpr int H_  = 256;

static constexpr int CL      = 8;
static constexpr int NB      = 4;
static constexpr int NCL     = 16;
static constexpr int THREADS = 384;   // 96 rows x 4 k-chunks(64)
static constexpr int APS     = 520;   // A-panel row stride (floats)
static constexpr int ACS     = 5;     // acc row stride -> conflict-free
static constexpr int XSLAB   = 4 * 96 * ACS;

typedef unsigned long long u64;

__device__ __forceinline__ void fma2(u64 &acc, u64 a, u64 b) {
    asm("fma.rn.f32x2 %0, %1, %2, %0;" : "+l"(acc) : "l"(a), "l"(b));
}
__device__ __forceinline__ float sum2(u64 v) {
    float lo, hi;
    asm("mov.b64 {%0,%1}, %2;" : "=f"(lo), "=f"(hi) : "l"(v));
    return lo + hi;
}
__device__ __forceinline__ uint32_t smem_u32(const void* p) {
    return (uint32_t)__cvta_generic_to_shared(p);
}
__device__ __forceinline__ void st_remote_f32(uint32_t laddr, int rank, float v) {
    uint32_t raddr;
    asm("mapa.shared::cluster.u32 %0, %1, %2;" : "=r"(raddr) : "r"(laddr), "r"(rank));
    asm volatile("st.shared::cluster.f32 [%0], %1;" :: "r"(raddr), "f"(v));
}
__device__ __forceinline__ void cluster_arrive_() {
    asm volatile("barrier.cluster.arrive.aligned;" ::: "memory");
}
__device__ __forceinline__ void cluster_wait_() {
    asm volatile("barrier.cluster.wait.aligned;" ::: "memory");
}
__device__ __forceinline__ uint32_t ctarank_() {
    uint32_t r;
    asm("mov.u32 %0, %%cluster_ctarank;" : "=r"(r));
    return r;
}
__device__ __forceinline__ float sigmoidf_(float x) {
    return 1.0f / (1.0f + __expf(-x));
}
__device__ __forceinline__ float tanhf_fast_(float x) {
    return 1.0f - 2.0f / (1.0f + __expf(2.0f * x));
}

__global__ void __launch_bounds__(THREADS, 1) __cluster_dims__(CL, 1, 1)
gru_persistent_kernel(const float* __restrict__ x,
                      const float* __restrict__ h0,
                      const float* __restrict__ Wih,
                      const float* __restrict__ bih,
                      const float* __restrict__ Whh,
                      const float* __restrict__ bhh,
                      float* __restrict__ out,
                      int out_size)
{
    __shared__ float Ap[2 * NB * APS];     // [parity][b][520]: h [0,256), x [256,512)
    __shared__ float accH[4 * 96 * ACS];   // [kc][row][b]
    __shared__ float accX[2 * XSLAB];      // [parity][kc][row][b]
    __shared__ float bias[4 * 32];         // [0]=r comb, [1]=hc, [2]=ic, [3]=u comb

    const int tid  = threadIdx.x;
    const int rank = (int)ctarank_();
    const int b0   = (blockIdx.x >> 3) * NB;

    const int kc   = tid / 96;             // 0..3 (warp-uniform; 96 = 3 warps)
    const int r    = tid - kc * 96;        // 0..95
    const int g    = ((r >> 5) << 8) + (rank << 5) + (r & 31);  // global fused row

    // ---- weights into registers: 64 floats of W_hh + 64 of W_ih (this row, k-chunk kc)
    ulonglong2 wh[16], wx[16];
    {
        const float* src_h = Whh + (size_t)g * 256 + (kc << 6);
        const float* src_x = Wih + (size_t)g * 256 + (kc << 6);
        #pragma unroll
        for (int k4 = 0; k4 < 16; ++k4) {
            wh[k4] = *(const ulonglong2*)(src_h + (k4 << 2));
            wx[k4] = *(const ulonglong2*)(src_x + (k4 << 2));
        }
    }

    // ---- combined biases
    if (tid < 32) {
        int jg = (rank << 5) + tid;
        bias[tid]      = bhh[jg]       + bih[jg];        // r gate combined
        bias[32 + tid] = bhh[256 + jg];                  // hc
        bias[64 + tid] = bih[256 + jg];                  // ic
        bias[96 + tid] = bhh[512 + jg] + bih[512 + jg];  // u gate combined
    }

    // ---- h0 + x(0) into Ap[0]
    for (int i4 = tid; i4 < NB * 64; i4 += THREADS) {
        int b = i4 >> 6, kk = i4 & 63;
        *(float4*)(Ap + b * APS + (kk << 2)) =
            *(const float4*)(h0 + (size_t)(b0 + b) * H_ + (kk << 2));
        *(float4*)(Ap + b * APS + 256 + (kk << 2)) =
            *(const float4*)(x + ((size_t)(b0 + b) * T_) * I_ + (kk << 2));
    }
    __syncthreads();

    // ---- prologue: gi(0) from Ap[0].x -> accX[0]; cp.async x(1) -> Ap[1].x
    {
        const float* A = Ap + 256 + (kc << 6);
        u64 a0 = 0, a1 = 0, a2 = 0, a3 = 0;
        #pragma unroll
        for (int k4 = 0; k4 < 16; ++k4) {
            ulonglong2 wv = wx[k4];
            ulonglong2 v0 = *(const ulonglong2*)(A + 0 * APS + (k4 << 2));
            ulonglong2 v1 = *(const ulonglong2*)(A + 1 * APS + (k4 << 2));
            fma2(a0, v0.x, wv.x); fma2(a0, v0.y, wv.y);
            fma2(a1, v1.x, wv.x); fma2(a1, v1.y, wv.y);
            ulonglong2 v2 = *(const ulonglong2*)(A + 2 * APS + (k4 << 2));
            ulonglong2 v3 = *(const ulonglong2*)(A + 3 * APS + (k4 << 2));
            fma2(a2, v2.x, wv.x); fma2(a2, v2.y, wv.y);
            fma2(a3, v3.x, wv.x); fma2(a3, v3.y, wv.y);
        }
        float* dst = accX + (kc * 96 + r) * ACS;
        dst[0] = sum2(a0); dst[1] = sum2(a1); dst[2] = sum2(a2); dst[3] = sum2(a3);
    }
    const uint32_t ap_u32 = smem_u32(Ap);
    if (tid < NB * 64) {
        int b = tid >> 6, kk = tid & 63;
        const float* gsrc = x + ((size_t)(b0 + b) * T_ + 1) * I_ + (kk << 2);
        uint32_t s = ap_u32 + (uint32_t)(((NB * APS) + b * APS + 256 + (kk << 2)) * 4);
        asm volatile("cp.async.ca.shared.global [%0], [%1], 16;" :: "r"(s), "l"(gsrc));
    }
    asm volatile("cp.async.commit_group;");

    const int eb  = tid >> 5;           // elementwise batch (tid<128)
    const int ej  = tid & 31;
    const int ejg = (rank << 5) + ej;
    const size_t BTH = (size_t)B_ * T_ * H_;

    for (int t = 0; t < T_; ++t) {
        const int p  = t & 1;
        const int pn = p ^ 1;

        // ---- 1. h-GEMM(t): all 12 warps, 64-K chunk each
        {
            const float* A = Ap + p * (NB * APS) + (kc << 6);
            u64 a0 = 0, a1 = 0, a2 = 0, a3 = 0;
            #pragma unroll
            for (int k4 = 0; k4 < 16; ++k4) {
                ulonglong2 wv = wh[k4];
                ulonglong2 v0 = *(const ulonglong2*)(A + 0 * APS + (k4 << 2));
                ulonglong2 v1 = *(const ulonglong2*)(A + 1 * APS + (k4 << 2));
                fma2(a0, v0.x, wv.x); fma2(a0, v0.y, wv.y);
                fma2(a1, v1.x, wv.x); fma2(a1, v1.y, wv.y);
                ulonglong2 v2 = *(const ulonglong2*)(A + 2 * APS + (k4 << 2));
                ulonglong2 v3 = *(const ulonglong2*)(A + 3 * APS + (k4 << 2));
                fma2(a2, v2.x, wv.x); fma2(a2, v2.y, wv.y);
                fma2(a3, v3.x, wv.x); fma2(a3, v3.y, wv.y);
            }
            float* dst = accH + (kc * 96 + r) * ACS;
            dst[0] = sum2(a0); dst[1] = sum2(a1); dst[2] = sum2(a2); dst[3] = sum2(a3);
        }
        __syncthreads();

        // ---- 2. elementwise GRU + DSMEM h-broadcast (threads 0..127)
        float hy;
        if (tid < 128) {
            const int b = eb, j = ej;
            const float* aX = accX + p * XSLAB;
            float rsum = bias[j], usum = bias[96 + j];
            float hc = bias[32 + j], ic = bias[64 + j];
            #pragma unroll
            for (int q = 0; q < 4; ++q) {
                const int base = q * 96;
                rsum += accH[(base + j) * ACS + b]      + aX[(base + j) * ACS + b];
                usum += accH[(base + 64 + j) * ACS + b] + aX[(base + 64 + j) * ACS + b];
                hc   += accH[(base + 32 + j) * ACS + b];
                ic   += aX  [(base + 32 + j) * ACS + b];
            }
            float rg = sigmoidf_(rsum);
            float u  = sigmoidf_(usum);
            float n  = tanhf_fast_(ic + rg * hc);

            float hold = Ap[p * (NB * APS) + b * APS + ejg];
            hy = hold + u * (n - hold);

            uint32_t laddr = ap_u32 + (uint32_t)((pn * (NB * APS) + b * APS + ejg) * 4);
            #pragma unroll
            for (int pr = 0; pr < CL; ++pr)
                st_remote_f32(laddr, pr, hy);
        }

        // ---- 3. arrive: releases the h-broadcasts cluster-wide
        cluster_arrive_();

        if (tid < 128)
            out[((size_t)(b0 + eb) * T_ + t) * H_ + ejg] = hy;

        // ---- 4. x-GEMM(t+1) in the barrier shadow (x(t+1) already landed)
        asm volatile("cp.async.wait_group 0;" ::: "memory");
        if (t + 1 < T_) {
            const float* A = Ap + pn * (NB * APS) + 256 + (kc << 6);
            u64 a0 = 0, a1 = 0, a2 = 0, a3 = 0;
            #pragma unroll
            for (int k4 = 0; k4 < 16; ++k4) {
                ulonglong2 wv = wx[k4];
                ulonglong2 v0 = *(const ulonglong2*)(A + 0 * APS + (k4 << 2));
                ulonglong2 v1 = *(const ulonglong2*)(A + 1 * APS + (k4 << 2));
                fma2(a0, v0.x, wv.x); fma2(a0, v0.y, wv.y);
                fma2(a1, v1.x, wv.x); fma2(a1, v1.y, wv.y);
                ulonglong2 v2 = *(const ulonglong2*)(A + 2 * APS + (k4 << 2));
                ulonglong2 v3 = *(const ulonglong2*)(A + 3 * APS + (k4 << 2));
                fma2(a2, v2.x, wv.x); fma2(a2, v2.y, wv.y);
                fma2(a3, v3.x, wv.x); fma2(a3, v3.y, wv.y);
            }
            float* dst = accX + pn * XSLAB + (kc * 96 + r) * ACS;
            dst[0] = sum2(a0); dst[1] = sum2(a1); dst[2] = sum2(a2); dst[3] = sum2(a3);
        }

        // ---- 5. prefetch x(t+2) into Ap[p].x
        if (t + 2 < T_ && tid < NB * 64) {
            int b = tid >> 6, kk = tid & 63;
            const float* gsrc = x + ((size_t)(b0 + b) * T_ + (t + 2)) * I_ + (kk << 2);
            uint32_t s = ap_u32 + (uint32_t)((p * (NB * APS) + b * APS + 256 + (kk << 2)) * 4);
            asm volatile("cp.async.ca.shared.global [%0], [%1], 16;" :: "r"(s), "l"(gsrc));
        }
        asm volatile("cp.async.commit_group;");

        // ---- 6. wait: peers' h(t+1) visible in Ap[pn].h
        cluster_wait_();
    }

    // ---- final hidden state: h(T) in parity 0 (T even)
    if (out_size >= (int)(BTH + (size_t)B_ * H_)) {
        for (int i = tid; i < NB * H_; i += THREADS) {
            int b = i >> 8, j = i & 255;
            out[BTH + (size_t)(b0 + b) * H_ + j] = Ap[b * APS + j];
        }
    }
}

extern "C" void kernel_launch(void* const* d_in, const int* in_sizes, int n_in,
                              void* d_out, int out_size) {
    const float* x    = (const float*)d_in[0];
    const float* h0   = (const float*)d_in[1];
    const float* Wih  = (const float*)d_in[2];
    const float* bih  = (const float*)d_in[3];
    const float* Whh  = (const float*)d_in[4];
    const float* bhh  = (const float*)d_in[5];
    float* out = (float*)d_out;

    gru_persistent_kernel<<<NCL * CL, THREADS>>>(
        x, h0, Wih, bih, Whh, bhh, out, out_size);
}

// round 10
// speedup vs baseline: 1.2586x; 1.2586x over previous
#include <cuda_runtime.h>
#include <cstdint>

// GRU: B=64, T=2048, I=256, H=256.  out = concat(out[B,T,H], hN[B,H]) fp32.
//
// 16 clusters x 8 CTAs (128 SMs). Cluster owns 4 batches; CTA rank owns
// j in [32r,32r+32) => fused rows {j,256+j,512+j} (96 rows x 512 fused K).
// Thread (r2, kc): rows {r2, r2+48}, fused-K chunk [64kc, 64kc+64) in regs
// (2 x 64 floats = 128 regs). Single fused GEMM per step (h and x parts
// together). Lanes in a warp carry 8 different kc -> conflict-free full
// 128B LDS wavefronts (A chunks padded to 68 floats).

static constexpr int B_  = 64;
static constexpr int T_  = 2048;
static constexpr int I_  = 256;
static constexpr int H_  = 256;

static constexpr int CL      = 8;
static constexpr int NB      = 4;
static constexpr int NCL     = 16;
static constexpr int THREADS = 384;   // 48 row-pairs x 8 k-chunks
static constexpr int CHS     = 68;    // chunk stride (64 floats + 4 pad)
static constexpr int APB     = 8 * CHS;      // 544 floats per batch
static constexpr int APP     = NB * APB;     // 2176 floats per parity
static constexpr int ACS     = 5;            // acc row stride

typedef unsigned long long u64;

__device__ __forceinline__ void fma2(u64 &acc, u64 a, u64 b) {
    asm("fma.rn.f32x2 %0, %1, %2, %0;" : "+l"(acc) : "l"(a), "l"(b));
}
__device__ __forceinline__ float sum2(u64 v) {
    float lo, hi;
    asm("mov.b64 {%0,%1}, %2;" : "=f"(lo), "=f"(hi) : "l"(v));
    return lo + hi;
}
__device__ __forceinline__ uint32_t smem_u32(const void* p) {
    return (uint32_t)__cvta_generic_to_shared(p);
}
__device__ __forceinline__ void st_remote_f32(uint32_t laddr, int rank, float v) {
    uint32_t raddr;
    asm("mapa.shared::cluster.u32 %0, %1, %2;" : "=r"(raddr) : "r"(laddr), "r"(rank));
    asm volatile("st.shared::cluster.f32 [%0], %1;" :: "r"(raddr), "f"(v));
}
__device__ __forceinline__ void cluster_arrive_() {
    asm volatile("barrier.cluster.arrive.aligned;" ::: "memory");
}
__device__ __forceinline__ void cluster_wait_() {
    asm volatile("barrier.cluster.wait.aligned;" ::: "memory");
}
__device__ __forceinline__ uint32_t ctarank_() {
    uint32_t r;
    asm("mov.u32 %0, %%cluster_ctarank;" : "=r"(r));
    return r;
}
__device__ __forceinline__ float sigmoidf_(float x) {
    return 1.0f / (1.0f + __expf(-x));
}
__device__ __forceinline__ float tanhf_fast_(float x) {
    return 1.0f - 2.0f / (1.0f + __expf(2.0f * x));
}

__global__ void __launch_bounds__(THREADS, 1) __cluster_dims__(CL, 1, 1)
gru_persistent_kernel(const float* __restrict__ x,
                      const float* __restrict__ h0,
                      const float* __restrict__ Wih,
                      const float* __restrict__ bih,
                      const float* __restrict__ Whh,
                      const float* __restrict__ bhh,
                      float* __restrict__ out,
                      int out_size)
{
    __shared__ float Ap[2 * APP];        // [parity][b][8 chunks][68]; ch<4: h, ch>=4: x
    __shared__ float accS[8 * 96 * ACS]; // [kc][row][b]
    __shared__ float bias[4 * 32];       // r-comb, hc, ic, u-comb

    const int tid  = threadIdx.x;
    const int rank = (int)ctarank_();
    const int b0   = (blockIdx.x >> 3) * NB;

    const int kc  = tid & 7;             // k-chunk 0..7 (lane-varying)
    const int r2  = tid >> 3;            // row-pair 0..47
    const int row0 = r2, row1 = r2 + 48;
    const int g0 = ((row0 >> 5) << 8) + (rank << 5) + (row0 & 31);
    const int g1 = ((row1 >> 5) << 8) + (rank << 5) + (row1 & 31);

    // ---- weights in registers: 2 rows x 64-float chunk
    ulonglong2 wA[16], wB[16];
    {
        const float* base = (kc < 4) ? Whh : Wih;
        const int colb = (kc & 3) << 6;
        const float* s0 = base + (size_t)g0 * 256 + colb;
        const float* s1 = base + (size_t)g1 * 256 + colb;
        #pragma unroll
        for (int k4 = 0; k4 < 16; ++k4) {
            wA[k4] = *(const ulonglong2*)(s0 + (k4 << 2));
            wB[k4] = *(const ulonglong2*)(s1 + (k4 << 2));
        }
    }

    // ---- combined biases
    if (tid < 32) {
        int jg = (rank << 5) + tid;
        bias[tid]      = bhh[jg]       + bih[jg];
        bias[32 + tid] = bhh[256 + jg];
        bias[64 + tid] = bih[256 + jg];
        bias[96 + tid] = bhh[512 + jg] + bih[512 + jg];
    }

    // ---- h0 + x(0) into Ap[0] (chunked layout)
    for (int i4 = tid; i4 < NB * 64; i4 += THREADS) {
        int b = i4 >> 6, kk = i4 & 63;
        int ch = kk >> 4, pos = (kk & 15) << 2;
        *(float4*)(Ap + b * APB + ch * CHS + pos) =
            *(const float4*)(h0 + (size_t)(b0 + b) * H_ + (kk << 2));
        *(float4*)(Ap + b * APB + (4 + ch) * CHS + pos) =
            *(const float4*)(x + ((size_t)(b0 + b) * T_) * I_ + (kk << 2));
    }

    // ---- cp.async x(1) -> Ap[1].x
    const uint32_t ap_u32 = smem_u32(Ap);
    if (tid < NB * 64) {
        int b = tid >> 6, kk = tid & 63;
        int ch = 4 + (kk >> 4), pos = (kk & 15) << 2;
        const float* gsrc = x + ((size_t)(b0 + b) * T_ + 1) * I_ + (kk << 2);
        uint32_t s = ap_u32 + (uint32_t)((APP + b * APB + ch * CHS + pos) * 4);
        asm volatile("cp.async.ca.shared.global [%0], [%1], 16;" :: "r"(s), "l"(gsrc));
    }
    asm volatile("cp.async.commit_group;");

    cluster_arrive_();
    cluster_wait_();

    const int eb  = tid >> 5;            // elementwise batch (tid<128)
    const int ej  = tid & 31;
    const int ejg = (rank << 5) + ej;
    const size_t BTH = (size_t)B_ * T_ * H_;

    for (int t = 0; t < T_; ++t) {
        const int p  = t & 1;
        const int pn = p ^ 1;

        // ---- 1. fused GEMM: 2 rows x 4 batches over this thread's 64-K chunk
        {
            const float* A = Ap + p * APP + kc * CHS;
            u64 a00 = 0, a01 = 0, a02 = 0, a03 = 0;
            u64 a10 = 0, a11 = 0, a12 = 0, a13 = 0;
            #pragma unroll
            for (int k4 = 0; k4 < 16; ++k4) {
                ulonglong2 wa = wA[k4], wb = wB[k4];
                ulonglong2 v0 = *(const ulonglong2*)(A + 0 * APB + (k4 << 2));
                ulonglong2 v1 = *(const ulonglong2*)(A + 1 * APB + (k4 << 2));
                fma2(a00, v0.x, wa.x); fma2(a00, v0.y, wa.y);
                fma2(a10, v0.x, wb.x); fma2(a10, v0.y, wb.y);
                fma2(a01, v1.x, wa.x); fma2(a01, v1.y, wa.y);
                fma2(a11, v1.x, wb.x); fma2(a11, v1.y, wb.y);
                ulonglong2 v2 = *(const ulonglong2*)(A + 2 * APB + (k4 << 2));
                ulonglong2 v3 = *(const ulonglong2*)(A + 3 * APB + (k4 << 2));
                fma2(a02, v2.x, wa.x); fma2(a02, v2.y, wa.y);
                fma2(a12, v2.x, wb.x); fma2(a12, v2.y, wb.y);
                fma2(a03, v3.x, wa.x); fma2(a03, v3.y, wa.y);
                fma2(a13, v3.x, wb.x); fma2(a13, v3.y, wb.y);
            }
            float* d0 = accS + (kc * 96 + row0) * ACS;
            float* d1 = accS + (kc * 96 + row1) * ACS;
            d0[0] = sum2(a00); d0[1] = sum2(a01); d0[2] = sum2(a02); d0[3] = sum2(a03);
            d1[0] = sum2(a10); d1[1] = sum2(a11); d1[2] = sum2(a12); d1[3] = sum2(a13);
        }
        __syncthreads();

        // ---- 2a. elementwise GRU + out + DSMEM h-broadcast (threads 0..127)
        if (tid < 128) {
            const int b = eb, j = ej;
            float rsum = bias[j], usum = bias[96 + j];
            float hc = bias[32 + j], ic = bias[64 + j];
            #pragma unroll
            for (int q = 0; q < 8; ++q) {
                const int base = q * 96;
                rsum += accS[(base + j) * ACS + b];
                usum += accS[(base + 64 + j) * ACS + b];
                float c = accS[(base + 32 + j) * ACS + b];
                if (q < 4) hc += c; else ic += c;
            }
            float rg = sigmoidf_(rsum);
            float u  = sigmoidf_(usum);
            float n  = tanhf_fast_(ic + rg * hc);

            const int hoff = b * APB + (ejg >> 6) * CHS + (ejg & 63);
            float hold = Ap[p * APP + hoff];
            float hy   = hold + u * (n - hold);

            out[((size_t)(b0 + b) * T_ + t) * H_ + ejg] = hy;

            uint32_t laddr = ap_u32 + (uint32_t)((pn * APP + hoff) * 4);
            #pragma unroll
            for (int pr = 0; pr < CL; ++pr)
                st_remote_f32(laddr, pr, hy);
        }
        // ---- 2b. x(t+2) prefetch into Ap[p].x (threads 128..383)
        else if (t + 2 < T_ && tid < 128 + NB * 64) {
            int i4 = tid - 128;
            int b = i4 >> 6, kk = i4 & 63;
            int ch = 4 + (kk >> 4), pos = (kk & 15) << 2;
            const float* gsrc = x + ((size_t)(b0 + b) * T_ + (t + 2)) * I_ + (kk << 2);
            uint32_t s = ap_u32 + (uint32_t)((p * APP + b * APB + ch * CHS + pos) * 4);
            asm volatile("cp.async.ca.shared.global [%0], [%1], 16;" :: "r"(s), "l"(gsrc));
        }
        asm volatile("cp.async.commit_group;");
        asm volatile("cp.async.wait_group 1;" ::: "memory");  // x(t+1) landed

        // ---- 3. cluster barrier: releases h-broadcasts, acquires peers'
        cluster_arrive_();
        cluster_wait_();
    }

    // ---- final hidden state: h(T) in parity 0 (T even)
    if (out_size >= (int)(BTH + (size_t)B_ * H_)) {
        for (int i = tid; i < NB * H_; i += THREADS) {
            int b = i >> 8, j = i & 255;
            out[BTH + (size_t)(b0 + b) * H_ + j] =
                Ap[b * APB + (j >> 6) * CHS + (j & 63)];
        }
    }
}

extern "C" void kernel_launch(void* const* d_in, const int* in_sizes, int n_in,
                              void* d_out, int out_size) {
    const float* x    = (const float*)d_in[0];
    const float* h0   = (const float*)d_in[1];
    const float* Wih  = (const float*)d_in[2];
    const float* bih  = (const float*)d_in[3];
    const float* Whh  = (const float*)d_in[4];
    const float* bhh  = (const float*)d_in[5];
    float* out = (float*)d_out;

    gru_persistent_kernel<<<NCL * CL, THREADS>>>(
        x, h0, Wih, bih, Whh, bhh, out, out_size);
}

// round 11
// speedup vs baseline: 1.4442x; 1.1474x over previous
#include <cuda_runtime.h>
#include <cstdint>

// GRU: B=64, T=2048, I=256, H=256.  out = concat(out[B,T,H], hN[B,H]) fp32.
//
// 16 clusters x 8 CTAs (128 SMs). Cluster owns 4 batches; CTA rank owns
// j in [32r,32r+32) => fused rows {j,256+j,512+j} (96 rows x 512 fused K).
// Thread (r2, kc): rows {r2, r2+48}, fused-K chunk [64kc,64kc+64) in regs.
// GEMM in two batch-halves to keep live regs low (no spill under the
// 170-reg cap). All SMEM access patterns bank-conflict-free:
//   A loads: CHS=68  -> banks 4*kc + 4*k4      (full 128B wavefronts)
//   acc    : slab 484 -> banks 4*kc + 5*row + b (injective per warp)

static constexpr int B_  = 64;
static constexpr int T_  = 2048;
static constexpr int I_  = 256;
static constexpr int H_  = 256;

static constexpr int CL      = 8;
static constexpr int NB      = 4;
static constexpr int NCL     = 16;
static constexpr int THREADS = 384;   // 48 row-pairs x 8 k-chunks
static constexpr int CHS     = 68;    // A chunk stride (64 + 4 pad)
static constexpr int APB     = 8 * CHS;      // 544 floats per batch
static constexpr int APP     = NB * APB;     // per parity
static constexpr int ARS     = 5;            // acc row stride
static constexpr int ASLAB   = 96 * ARS + 4; // 484: kc slab stride (mod 32 = 4)

typedef unsigned long long u64;

__device__ __forceinline__ void fma2(u64 &acc, u64 a, u64 b) {
    asm("fma.rn.f32x2 %0, %1, %2, %0;" : "+l"(acc) : "l"(a), "l"(b));
}
__device__ __forceinline__ float sum2(u64 v) {
    float lo, hi;
    asm("mov.b64 {%0,%1}, %2;" : "=f"(lo), "=f"(hi) : "l"(v));
    return lo + hi;
}
__device__ __forceinline__ uint32_t smem_u32(const void* p) {
    return (uint32_t)__cvta_generic_to_shared(p);
}
__device__ __forceinline__ void st_remote_f32(uint32_t laddr, int rank, float v) {
    uint32_t raddr;
    asm("mapa.shared::cluster.u32 %0, %1, %2;" : "=r"(raddr) : "r"(laddr), "r"(rank));
    asm volatile("st.shared::cluster.f32 [%0], %1;" :: "r"(raddr), "f"(v));
}
__device__ __forceinline__ void cluster_arrive_() {
    asm volatile("barrier.cluster.arrive.aligned;" ::: "memory");
}
__device__ __forceinline__ void cluster_wait_() {
    asm volatile("barrier.cluster.wait.aligned;" ::: "memory");
}
__device__ __forceinline__ uint32_t ctarank_() {
    uint32_t r;
    asm("mov.u32 %0, %%cluster_ctarank;" : "=r"(r));
    return r;
}
__device__ __forceinline__ float sigmoidf_(float x) {
    return 1.0f / (1.0f + __expf(-x));
}
__device__ __forceinline__ float tanhf_fast_(float x) {
    return 1.0f - 2.0f / (1.0f + __expf(2.0f * x));
}

__global__ void __launch_bounds__(THREADS, 1) __cluster_dims__(CL, 1, 1)
gru_persistent_kernel(const float* __restrict__ x,
                      const float* __restrict__ h0,
                      const float* __restrict__ Wih,
                      const float* __restrict__ bih,
                      const float* __restrict__ Whh,
                      const float* __restrict__ bhh,
                      float* __restrict__ out,
                      int out_size)
{
    __shared__ float Ap[2 * APP];       // [parity][b][8 chunks][68]; ch<4: h, ch>=4: x
    __shared__ float accS[8 * ASLAB];   // [kc slab 484][row*5 + b]
    __shared__ float bias[4 * 32];      // r-comb, hc, ic, u-comb

    const int tid  = threadIdx.x;
    const int rank = (int)ctarank_();
    const int b0   = (blockIdx.x >> 3) * NB;

    const int kc  = tid & 7;            // k-chunk 0..7 (lane-varying)
    const int r2  = tid >> 3;           // row-pair 0..47
    const int row0 = r2, row1 = r2 + 48;
    const int g0 = ((row0 >> 5) << 8) + (rank << 5) + (row0 & 31);
    const int g1 = ((row1 >> 5) << 8) + (rank << 5) + (row1 & 31);

    // ---- weights in registers: 2 rows x 64-float chunk
    ulonglong2 wA[16], wB[16];
    {
        const float* base = (kc < 4) ? Whh : Wih;
        const int colb = (kc & 3) << 6;
        const float* s0 = base + (size_t)g0 * 256 + colb;
        const float* s1 = base + (size_t)g1 * 256 + colb;
        #pragma unroll
        for (int k4 = 0; k4 < 16; ++k4) {
            wA[k4] = *(const ulonglong2*)(s0 + (k4 << 2));
            wB[k4] = *(const ulonglong2*)(s1 + (k4 << 2));
        }
    }

    // ---- combined biases
    if (tid < 32) {
        int jg = (rank << 5) + tid;
        bias[tid]      = bhh[jg]       + bih[jg];
        bias[32 + tid] = bhh[256 + jg];
        bias[64 + tid] = bih[256 + jg];
        bias[96 + tid] = bhh[512 + jg] + bih[512 + jg];
    }

    // ---- h0 + x(0) into Ap[0] (chunked layout)
    for (int i4 = tid; i4 < NB * 64; i4 += THREADS) {
        int b = i4 >> 6, kk = i4 & 63;
        int ch = kk >> 4, pos = (kk & 15) << 2;
        *(float4*)(Ap + b * APB + ch * CHS + pos) =
            *(const float4*)(h0 + (size_t)(b0 + b) * H_ + (kk << 2));
        *(float4*)(Ap + b * APB + (4 + ch) * CHS + pos) =
            *(const float4*)(x + ((size_t)(b0 + b) * T_) * I_ + (kk << 2));
    }

    // ---- cp.async x(1) -> Ap[1].x
    const uint32_t ap_u32 = smem_u32(Ap);
    if (tid < NB * 64) {
        int b = tid >> 6, kk = tid & 63;
        int ch = 4 + (kk >> 4), pos = (kk & 15) << 2;
        const float* gsrc = x + ((size_t)(b0 + b) * T_ + 1) * I_ + (kk << 2);
        uint32_t s = ap_u32 + (uint32_t)((APP + b * APB + ch * CHS + pos) * 4);
        asm volatile("cp.async.ca.shared.global [%0], [%1], 16;" :: "r"(s), "l"(gsrc));
    }
    asm volatile("cp.async.commit_group;");

    cluster_arrive_();
    cluster_wait_();

    const int eb  = tid >> 5;           // elementwise batch (tid<128)
    const int ej  = tid & 31;
    const int ejg = (rank << 5) + ej;
    const size_t BTH = (size_t)B_ * T_ * H_;

    for (int t = 0; t < T_; ++t) {
        const int p  = t & 1;
        const int pn = p ^ 1;

        // ---- 1. fused GEMM, two batch-halves (low live-reg pressure)
        {
            const float* A = Ap + p * APP + kc * CHS;
            float* dst0 = accS + kc * ASLAB + row0 * ARS;
            float* dst1 = accS + kc * ASLAB + row1 * ARS;
            #pragma unroll
            for (int h = 0; h < 2; ++h) {
                const float* Ab = A + (h * 2) * APB;
                u64 a00 = 0, a01 = 0, a10 = 0, a11 = 0;
                #pragma unroll
                for (int k4 = 0; k4 < 16; ++k4) {
                    ulonglong2 wa = wA[k4], wb = wB[k4];
                    ulonglong2 v0 = *(const ulonglong2*)(Ab + (k4 << 2));
                    ulonglong2 v1 = *(const ulonglong2*)(Ab + APB + (k4 << 2));
                    fma2(a00, v0.x, wa.x); fma2(a00, v0.y, wa.y);
                    fma2(a10, v0.x, wb.x); fma2(a10, v0.y, wb.y);
                    fma2(a01, v1.x, wa.x); fma2(a01, v1.y, wa.y);
                    fma2(a11, v1.x, wb.x); fma2(a11, v1.y, wb.y);
                }
                dst0[h * 2 + 0] = sum2(a00);
                dst0[h * 2 + 1] = sum2(a01);
                dst1[h * 2 + 0] = sum2(a10);
                dst1[h * 2 + 1] = sum2(a11);
            }
        }
        __syncthreads();

        // ---- 2a. elementwise GRU + out + DSMEM h-broadcast (threads 0..127)
        if (tid < 128) {
            const int b = eb, j = ej;
            float rsum = bias[j], usum = bias[96 + j];
            float hc = bias[32 + j], ic = bias[64 + j];
            #pragma unroll
            for (int q = 0; q < 8; ++q) {
                const float* s = accS + q * ASLAB;
                rsum += s[j * ARS + b];
                usum += s[(64 + j) * ARS + b];
                float c = s[(32 + j) * ARS + b];
                if (q < 4) hc += c; else ic += c;
            }
            float rg = sigmoidf_(rsum);
            float u  = sigmoidf_(usum);
            float n  = tanhf_fast_(ic + rg * hc);

            const int hoff = b * APB + (ejg >> 6) * CHS + (ejg & 63);
            float hold = Ap[p * APP + hoff];
            float hy   = hold + u * (n - hold);

            out[((size_t)(b0 + b) * T_ + t) * H_ + ejg] = hy;

            uint32_t laddr = ap_u32 + (uint32_t)((pn * APP + hoff) * 4);
            #pragma unroll
            for (int pr = 0; pr < CL; ++pr)
                st_remote_f32(laddr, pr, hy);
        }
        // ---- 2b. x(t+2) prefetch into Ap[p].x (threads 128..383)
        else if (t + 2 < T_ && tid < 128 + NB * 64) {
            int i4 = tid - 128;
            int b = i4 >> 6, kk = i4 & 63;
            int ch = 4 + (kk >> 4), pos = (kk & 15) << 2;
            const float* gsrc = x + ((size_t)(b0 + b) * T_ + (t + 2)) * I_ + (kk << 2);
            uint32_t s = ap_u32 + (uint32_t)((p * APP + b * APB + ch * CHS + pos) * 4);
            asm volatile("cp.async.ca.shared.global [%0], [%1], 16;" :: "r"(s), "l"(gsrc));
        }
        asm volatile("cp.async.commit_group;");
        asm volatile("cp.async.wait_group 1;" ::: "memory");  // x(t+1) landed

        // ---- 3. cluster barrier: releases h-broadcasts, acquires peers'
        cluster_arrive_();
        cluster_wait_();
    }

    // ---- final hidden state: h(T) in parity 0 (T even)
    if (out_size >= (int)(BTH + (size_t)B_ * H_)) {
        for (int i = tid; i < NB * H_; i += THREADS) {
            int b = i >> 8, j = i & 255;
            out[BTH + (size_t)(b0 + b) * H_ + j] =
                Ap[b * APB + (j >> 6) * CHS + (j & 63)];
        }
    }
}

extern "C" void kernel_launch(void* const* d_in, const int* in_sizes, int n_in,
                              void* d_out, int out_size) {
    const float* x    = (const float*)d_in[0];
    const float* h0   = (const float*)d_in[1];
    const float* Wih  = (const float*)d_in[2];
    const float* bih  = (const float*)d_in[3];
    const float* Whh  = (const float*)d_in[4];
    const float* bhh  = (const float*)d_in[5];
    float* out = (float*)d_out;

    gru_persistent_kernel<<<NCL * CL, THREADS>>>(
        x, h0, Wih, bih, Whh, bhh, out, out_size);
}

// round 12
// speedup vs baseline: 1.7125x; 1.1858x over previous
#include <cuda_runtime.h>
#include <cstdint>

// GRU: B=64, T=2048, I=256, H=256.  out = concat(out[B,T,H], hN[B,H]) fp32.
//
// 16 clusters x 8 CTAs (128 SMs). Cluster owns 4 batches; CTA rank owns
// j in [32r,32r+32) => fused rows {j,256+j,512+j} (96 rows x 512 fused K).
// Thread (rg, kc): 4 rows {rg, rg+24, rg+48, rg+72}, fused-K chunk
// [32kc, 32kc+32) in registers (4 x 32 = 128 floats). Each A float4 load
// feeds 8 fma2 (4 rows x 2) -> A-operand LDS wavefronts halved vs 2-row tiling.
// Bank layout: A chunk stride 36 (phase-disjoint quads), acc slab stride 482
// (all-32-lane conflict-free stores), acc row stride 5.

static constexpr int B_  = 64;
static constexpr int T_  = 2048;
static constexpr int I_  = 256;
static constexpr int H_  = 256;

static constexpr int CL      = 8;
static constexpr int NB      = 4;
static constexpr int NCL     = 16;
static constexpr int THREADS = 384;   // 24 row-groups x 16 k-chunks
static constexpr int CHS     = 36;    // A chunk stride (32 + 4 pad)
static constexpr int APB     = 16 * CHS;     // 576 floats per batch
static constexpr int APP     = NB * APB;     // 2304 per parity
static constexpr int ARS     = 5;            // acc row stride
static constexpr int ASLAB   = 96 * ARS + 2; // 482 (mod 32 = 2)

typedef unsigned long long u64;

__device__ __forceinline__ void fma2(u64 &acc, u64 a, u64 b) {
    asm("fma.rn.f32x2 %0, %1, %2, %0;" : "+l"(acc) : "l"(a), "l"(b));
}
__device__ __forceinline__ float sum2(u64 v) {
    float lo, hi;
    asm("mov.b64 {%0,%1}, %2;" : "=f"(lo), "=f"(hi) : "l"(v));
    return lo + hi;
}
__device__ __forceinline__ uint32_t smem_u32(const void* p) {
    return (uint32_t)__cvta_generic_to_shared(p);
}
__device__ __forceinline__ void st_remote_f32(uint32_t laddr, int rank, float v) {
    uint32_t raddr;
    asm("mapa.shared::cluster.u32 %0, %1, %2;" : "=r"(raddr) : "r"(laddr), "r"(rank));
    asm volatile("st.shared::cluster.f32 [%0], %1;" :: "r"(raddr), "f"(v));
}
__device__ __forceinline__ void cluster_arrive_() {
    asm volatile("barrier.cluster.arrive.aligned;" ::: "memory");
}
__device__ __forceinline__ void cluster_wait_() {
    asm volatile("barrier.cluster.wait.aligned;" ::: "memory");
}
__device__ __forceinline__ uint32_t ctarank_() {
    uint32_t r;
    asm("mov.u32 %0, %%cluster_ctarank;" : "=r"(r));
    return r;
}
__device__ __forceinline__ float sigmoidf_(float x) {
    return 1.0f / (1.0f + __expf(-x));
}
__device__ __forceinline__ float tanhf_fast_(float x) {
    return 1.0f - 2.0f / (1.0f + __expf(2.0f * x));
}

__global__ void __launch_bounds__(THREADS, 1) __cluster_dims__(CL, 1, 1)
gru_persistent_kernel(const float* __restrict__ x,
                      const float* __restrict__ h0,
                      const float* __restrict__ Wih,
                      const float* __restrict__ bih,
                      const float* __restrict__ Whh,
                      const float* __restrict__ bhh,
                      float* __restrict__ out,
                      int out_size)
{
    __shared__ float Ap[2 * APP];        // [parity][b][16 chunks][36]; ch<8: h, ch>=8: x
    __shared__ float accS[16 * ASLAB];   // [kc slab 482][row*5 + b]
    __shared__ float bias[4 * 32];       // r-comb, hc, ic, u-comb

    const int tid  = threadIdx.x;
    const int rank = (int)ctarank_();
    const int b0   = (blockIdx.x >> 3) * NB;

    const int kc = tid & 15;             // k-chunk 0..15 (lane-varying)
    const int rg = tid >> 4;             // row-group 0..23; rows rg + 24m

    // ---- weights in registers: 4 rows x 32-float chunk = 128 floats
    ulonglong2 w[4][8];
    {
        const float* base = (kc < 8) ? Whh : Wih;
        const int colb = (kc & 7) << 5;
        #pragma unroll
        for (int m = 0; m < 4; ++m) {
            int row = rg + 24 * m;
            int g   = ((row >> 5) << 8) + (rank << 5) + (row & 31);
            const float* src = base + (size_t)g * 256 + colb;
            #pragma unroll
            for (int k4 = 0; k4 < 8; ++k4)
                w[m][k4] = *(const ulonglong2*)(src + (k4 << 2));
        }
    }

    // ---- combined biases
    if (tid < 32) {
        int jg = (rank << 5) + tid;
        bias[tid]      = bhh[jg]       + bih[jg];
        bias[32 + tid] = bhh[256 + jg];
        bias[64 + tid] = bih[256 + jg];
        bias[96 + tid] = bhh[512 + jg] + bih[512 + jg];
    }

    // ---- h0 + x(0) into Ap[0] (chunked layout, 32-float chunks)
    for (int i4 = tid; i4 < NB * 64; i4 += THREADS) {
        int b = i4 >> 6, kk = i4 & 63;
        int ch = kk >> 3, pos = (kk & 7) << 2;
        *(float4*)(Ap + b * APB + ch * CHS + pos) =
            *(const float4*)(h0 + (size_t)(b0 + b) * H_ + (kk << 2));
        *(float4*)(Ap + b * APB + (8 + ch) * CHS + pos) =
            *(const float4*)(x + ((size_t)(b0 + b) * T_) * I_ + (kk << 2));
    }

    // ---- cp.async x(1) -> Ap[1].x
    const uint32_t ap_u32 = smem_u32(Ap);
    if (tid < NB * 64) {
        int b = tid >> 6, kk = tid & 63;
        int ch = 8 + (kk >> 3), pos = (kk & 7) << 2;
        const float* gsrc = x + ((size_t)(b0 + b) * T_ + 1) * I_ + (kk << 2);
        uint32_t s = ap_u32 + (uint32_t)((APP + b * APB + ch * CHS + pos) * 4);
        asm volatile("cp.async.ca.shared.global [%0], [%1], 16;" :: "r"(s), "l"(gsrc));
    }
    asm volatile("cp.async.commit_group;");

    cluster_arrive_();
    cluster_wait_();

    const int eb  = tid >> 5;            // elementwise batch (tid<128)
    const int ej  = tid & 31;
    const int ejg = (rank << 5) + ej;
    const size_t BTH = (size_t)B_ * T_ * H_;

    for (int t = 0; t < T_; ++t) {
        const int p  = t & 1;
        const int pn = p ^ 1;

        // ---- 1. fused GEMM: 4 rows x 4 batches over this thread's 32-K chunk,
        //         two batch-halves to bound live registers
        {
            const float* A = Ap + p * APP + kc * CHS;
            #pragma unroll
            for (int h = 0; h < 2; ++h) {
                const float* Aa = A + (2 * h) * APB;
                const float* Ab = Aa + APB;
                u64 c00 = 0, c01 = 0, c10 = 0, c11 = 0;
                u64 c20 = 0, c21 = 0, c30 = 0, c31 = 0;
                #pragma unroll
                for (int k4 = 0; k4 < 8; ++k4) {
                    ulonglong2 va = *(const ulonglong2*)(Aa + (k4 << 2));
                    ulonglong2 vb = *(const ulonglong2*)(Ab + (k4 << 2));
                    ulonglong2 w0 = w[0][k4], w1 = w[1][k4];
                    fma2(c00, va.x, w0.x); fma2(c00, va.y, w0.y);
                    fma2(c01, vb.x, w0.x); fma2(c01, vb.y, w0.y);
                    fma2(c10, va.x, w1.x); fma2(c10, va.y, w1.y);
                    fma2(c11, vb.x, w1.x); fma2(c11, vb.y, w1.y);
                    ulonglong2 w2 = w[2][k4], w3 = w[3][k4];
                    fma2(c20, va.x, w2.x); fma2(c20, va.y, w2.y);
                    fma2(c21, vb.x, w2.x); fma2(c21, vb.y, w2.y);
                    fma2(c30, va.x, w3.x); fma2(c30, va.y, w3.y);
                    fma2(c31, vb.x, w3.x); fma2(c31, vb.y, w3.y);
                }
                float* s0 = accS + kc * ASLAB + (rg +  0) * ARS + 2 * h;
                float* s1 = accS + kc * ASLAB + (rg + 24) * ARS + 2 * h;
                float* s2 = accS + kc * ASLAB + (rg + 48) * ARS + 2 * h;
                float* s3 = accS + kc * ASLAB + (rg + 72) * ARS + 2 * h;
                s0[0] = sum2(c00); s0[1] = sum2(c01);
                s1[0] = sum2(c10); s1[1] = sum2(c11);
                s2[0] = sum2(c20); s2[1] = sum2(c21);
                s3[0] = sum2(c30); s3[1] = sum2(c31);
            }
        }
        __syncthreads();

        // ---- 2a. elementwise GRU + out + DSMEM h-broadcast (threads 0..127)
        if (tid < 128) {
            const int b = eb, j = ej;
            float rsum = bias[j], usum = bias[96 + j];
            float hc = bias[32 + j], ic = bias[64 + j];
            #pragma unroll
            for (int q = 0; q < 16; ++q) {
                const float* s = accS + q * ASLAB;
                rsum += s[j * ARS + b];
                usum += s[(64 + j) * ARS + b];
                float c = s[(32 + j) * ARS + b];
                if (q < 8) hc += c; else ic += c;
            }
            float rgt = sigmoidf_(rsum);
            float u   = sigmoidf_(usum);
            float n   = tanhf_fast_(ic + rgt * hc);

            const int hoff = b * APB + (ejg >> 5) * CHS + (ejg & 31);
            float hold = Ap[p * APP + hoff];
            float hy   = hold + u * (n - hold);

            out[((size_t)(b0 + b) * T_ + t) * H_ + ejg] = hy;

            uint32_t laddr = ap_u32 + (uint32_t)((pn * APP + hoff) * 4);
            #pragma unroll
            for (int pr = 0; pr < CL; ++pr)
                st_remote_f32(laddr, pr, hy);
        }
        // ---- 2b. x(t+2) prefetch into Ap[p].x (threads 128..383)
        else if (t + 2 < T_ && tid < 128 + NB * 64) {
            int i4 = tid - 128;
            int b = i4 >> 6, kk = i4 & 63;
            int ch = 8 + (kk >> 3), pos = (kk & 7) << 2;
            const float* gsrc = x + ((size_t)(b0 + b) * T_ + (t + 2)) * I_ + (kk << 2);
            uint32_t s = ap_u32 + (uint32_t)((p * APP + b * APB + ch * CHS + pos) * 4);
            asm volatile("cp.async.ca.shared.global [%0], [%1], 16;" :: "r"(s), "l"(gsrc));
        }
        asm volatile("cp.async.commit_group;");
        asm volatile("cp.async.wait_group 1;" ::: "memory");  // x(t+1) landed

        // ---- 3. cluster barrier: releases h-broadcasts, acquires peers'
        cluster_arrive_();
        cluster_wait_();
    }

    // ---- final hidden state: h(T) in parity 0 (T even)
    if (out_size >= (int)(BTH + (size_t)B_ * H_)) {
        for (int i = tid; i < NB * H_; i += THREADS) {
            int b = i >> 8, j = i & 255;
            out[BTH + (size_t)(b0 + b) * H_ + j] =
                Ap[b * APB + (j >> 5) * CHS + (j & 31)];
        }
    }
}

extern "C" void kernel_launch(void* const* d_in, const int* in_sizes, int n_in,
                              void* d_out, int out_size) {
    const float* x    = (const float*)d_in[0];
    const float* h0   = (const float*)d_in[1];
    const float* Wih  = (const float*)d_in[2];
    const float* bih  = (const float*)d_in[3];
    const float* Whh  = (const float*)d_in[4];
    const float* bhh  = (const float*)d_in[5];
    float* out = (float*)d_out;

    gru_persistent_kernel<<<NCL * CL, THREADS>>>(
        x, h0, Wih, bih, Whh, bhh, out, out_size);
}